// round 7
// baseline (speedup 1.0000x reference)
#include <cuda_runtime.h>
#include <cuda_bf16.h>
#include <cstdint>

#define B_      4
#define HW_     4096
#define C_      256
#define D_      64
#define TJ      64
#define NT      (HW_/TJ)
#define THREADS 512
#define SHIFT   28.0f

// dynamic smem layout (bytes)
#define SM_QHI  0
#define SM_QLO  16384
#define SM_BUF0 32768
#define OFF_KHI 0
#define OFF_KLO 8192
#define OFF_VHI 16384
#define OFF_VLO 49152
#define BUF_SZ  81920
#define SM_TOTAL (SM_BUF0 + 2*BUF_SZ)   // 196608 B

#define SW(x) ((x) ^ (((x) >> 3) & 0x70))

// pre-converted bf16 splits
__device__ __align__(16) __nv_bfloat16 g_Khi[B_*HW_*D_];
__device__ __align__(16) __nv_bfloat16 g_Klo[B_*HW_*D_];
__device__ __align__(16) __nv_bfloat16 g_Vthi[B_*C_*HW_];   // [b][c][j]
__device__ __align__(16) __nv_bfloat16 g_Vtlo[B_*C_*HW_];

__device__ __forceinline__ uint32_t smem_u32(const void* p) {
    uint32_t a;
    asm("{ .reg .u64 t; cvta.to.shared.u64 t, %1; cvt.u32.u64 %0, t; }" : "=r"(a) : "l"(p));
    return a;
}
__device__ __forceinline__ void cp16(uint32_t dst, const void* src) {
    asm volatile("cp.async.cg.shared.global [%0], [%1], 16;" :: "r"(dst), "l"(src));
}
#define CP_COMMIT() asm volatile("cp.async.commit_group;" ::: "memory")
#define CP_WAIT1()  asm volatile("cp.async.wait_group 1;" ::: "memory")

__device__ __forceinline__ void ldsm4(uint32_t* r, uint32_t addr) {
    asm volatile("ldmatrix.sync.aligned.m8n8.x4.shared.b16 {%0,%1,%2,%3}, [%4];"
                 : "=r"(r[0]), "=r"(r[1]), "=r"(r[2]), "=r"(r[3]) : "r"(addr));
}
__device__ __forceinline__ void mma16816(float* c, const uint32_t* a, const uint32_t* b) {
    asm volatile("mma.sync.aligned.m16n8k16.row.col.f32.bf16.bf16.f32 "
                 "{%0,%1,%2,%3}, {%4,%5,%6,%7}, {%8,%9}, {%0,%1,%2,%3};"
                 : "+f"(c[0]), "+f"(c[1]), "+f"(c[2]), "+f"(c[3])
                 : "r"(a[0]), "r"(a[1]), "r"(a[2]), "r"(a[3]), "r"(b[0]), "r"(b[1]));
}

// pack two floats -> bf16x2 (lo half = a)
__device__ __forceinline__ uint32_t pk2(float a, float b) {
    uint32_t r;
    asm("cvt.rn.bf16x2.f32 %0, %1, %2;" : "=r"(r) : "f"(b), "f"(a));
    return r;
}
__device__ __forceinline__ void split2(float a, float b, uint32_t& hi, uint32_t& lo) {
    hi = pk2(a, b);
    float ra = a - __uint_as_float(hi << 16);
    float rb = b - __uint_as_float(hi & 0xffff0000u);
    lo = pk2(ra, rb);
}

// ---- pre-kernel: split x_query -> Khi/Klo (512*256*8 = exactly 1048576 elems) ----
__global__ void __launch_bounds__(256) conv_k_kernel(const float* __restrict__ xq) {
    size_t id = (size_t)blockIdx.x * 256 + threadIdx.x;
    const float4* src = (const float4*)xq + id * 2;
    float4 a = src[0], b = src[1];
    uint4 hi, lo;
    split2(a.x, a.y, hi.x, lo.x);
    split2(a.z, a.w, hi.y, lo.y);
    split2(b.x, b.y, hi.z, lo.z);
    split2(b.z, b.w, hi.w, lo.w);
    ((uint4*)g_Khi)[id] = hi;
    ((uint4*)g_Klo)[id] = lo;
}

// ---- pre-kernel: transpose+split x_value -> Vthi/Vtlo ----
__global__ void __launch_bounds__(256) conv_v_kernel(const float* __restrict__ xv) {
    __shared__ float tile[32][33];
    const int j0 = blockIdx.x * 32, c0 = blockIdx.y * 32, b = blockIdx.z;
    const int tx = threadIdx.x, ty = threadIdx.y;   // 32 x 8
    #pragma unroll
    for (int r = 0; r < 4; r++) {
        const int j = j0 + ty + r * 8;
        tile[ty + r * 8][tx] = xv[((size_t)(b * HW_ + j)) * C_ + c0 + tx];
    }
    __syncthreads();
    #pragma unroll
    for (int r = 0; r < 4; r++) {
        const int c = c0 + ty + r * 8;
        const float v = tile[tx][ty + r * 8];
        const __nv_bfloat16 h = __float2bfloat16(v);
        const size_t o = ((size_t)(b * C_ + c)) * HW_ + j0 + tx;
        g_Vthi[o] = h;
        g_Vtlo[o] = __float2bfloat16(v - __bfloat162float(h));
    }
}

__device__ __forceinline__ void load_K(uint32_t kbase, int b, int jt, int tid) {
    #pragma unroll
    for (int k = 0; k < 2; k++) {
        const int i = tid + k * 512;               // 1024 x 16B (hi+lo)
        const int half = i >> 9, rem = i & 511, row = rem >> 3, ch = rem & 7;
        const __nv_bfloat16* s = (half ? g_Klo : g_Khi)
                               + (((size_t)(b * HW_ + jt + row)) << 6) + ch * 8;
        cp16(kbase + (half ? OFF_KLO : OFF_KHI) + SW(row * 128 + ch * 16), s);
    }
}
__device__ __forceinline__ void load_V(uint32_t vbase, int b, int jt, int tid) {
    #pragma unroll
    for (int k = 0; k < 8; k++) {
        const int i = tid + k * 512;               // 4096 x 16B (hi+lo)
        const int half = i >> 11, rem = i & 2047, row = rem >> 3, ch = rem & 7;
        const __nv_bfloat16* s = (half ? g_Vtlo : g_Vthi)
                               + ((size_t)(b * C_ + row)) * HW_ + jt + ch * 8;
        cp16(vbase + (half ? OFF_VLO : OFF_VHI) + SW(row * 128 + ch * 16), s);
    }
}

__global__ void __launch_bounds__(THREADS, 1)
attn_mma_kernel(const float* __restrict__ g, const float* __restrict__ x,
                const float* __restrict__ pg, const float* __restrict__ kscal,
                float* __restrict__ out)
{
    extern __shared__ char smem[];
    const uint32_t sb = smem_u32(smem);
    const int tid   = threadIdx.x;
    const int warp  = tid >> 5, lane = tid & 31;
    const int wg    = warp >> 3;        // 0: c 0..127, 1: c 128..255
    const int mwarp = warp & 7;         // row-tile owner (16 rows)
    const int b     = blockIdx.x >> 5;
    const int row0  = (blockIdx.x & 31) * 128;

    // lane patterns for ldmatrix addressing
    const int a_r  = lane & 15;
    const int a_c2 = (lane >> 4) * 16;
    const int b_r  = (lane & 7) + ((lane >> 4) & 1) * 8;
    const int b_c2 = ((lane >> 3) & 1) * 16;

    uint32_t qoffh[4], qoffl[4];
    #pragma unroll
    for (int kk = 0; kk < 4; kk++) {
        const uint32_t o = SW((mwarp * 16 + a_r) * 128 + kk * 32 + a_c2);
        qoffh[kk] = sb + SM_QHI + o;
        qoffl[kk] = sb + SM_QLO + o;
    }

    // prologue tile loads: tile0 -> buf0, tile1 -> buf1
    load_K(sb + SM_BUF0, b, 0, tid);
    load_V(sb + SM_BUF0, b, 0, tid);
    CP_COMMIT();
    load_K(sb + SM_BUF0 + BUF_SZ, b, TJ, tid);
    load_V(sb + SM_BUF0 + BUF_SZ, b, TJ, tid);
    CP_COMMIT();

    // stage Q (load + split) into smem, overlapped with cp.async
    for (int i = tid; i < 4096; i += THREADS) {
        const int r = i >> 5, dp = i & 31;
        const float2 f = *(const float2*)&pg[((size_t)(b * HW_ + row0 + r)) * 64 + dp * 2];
        uint32_t h, l;
        split2(f.x, f.y, h, l);
        const uint32_t o = SW(r * 128 + dp * 4);
        *(uint32_t*)(smem + SM_QHI + o) = h;
        *(uint32_t*)(smem + SM_QLO + o) = l;
    }

    float oacc[64];                      // 16 rows x 4 regs x 8 cg (this wg's C-half)
    #pragma unroll
    for (int i = 0; i < 64; i++) oacc[i] = 0.0f;
    float lsum0 = 0.0f, lsum1 = 0.0f;

    for (int t = 0; t < NT; t++) {
        CP_WAIT1();
        __syncthreads();
        const int buf = t & 1;
        const uint32_t kb = sb + SM_BUF0 + buf * BUF_SZ;

        // ---- S = Q K^T (3-pass bf16 split) — computed by BOTH wgs (same rows) ----
        float sacc[32];
        #pragma unroll
        for (int i = 0; i < 32; i++) sacc[i] = 0.0f;

        #pragma unroll
        for (int kk = 0; kk < 4; kk++) {
            uint32_t qh[4], ql[4];
            ldsm4(qh, qoffh[kk]);
            ldsm4(ql, qoffl[kk]);
            #pragma unroll
            for (int ng = 0; ng < 4; ng++) {
                const uint32_t off = SW((ng * 16 + b_r) * 128 + kk * 32 + b_c2);
                uint32_t kh[4], kl[4];
                ldsm4(kh, kb + OFF_KHI + off);
                ldsm4(kl, kb + OFF_KLO + off);
                float* c0 = &sacc[(ng * 2) * 4];
                float* c1 = &sacc[(ng * 2 + 1) * 4];
                mma16816(c0, qh, kh + 0); mma16816(c1, qh, kh + 2);
                mma16816(c0, ql, kh + 0); mma16816(c1, ql, kh + 2);
                mma16816(c0, qh, kl + 0); mma16816(c1, qh, kl + 2);
            }
        }

        // ---- softmax (fixed shift) + pack P into bf16 hi/lo A-fragments ----
        uint32_t pah[16], pal[16];
        #pragma unroll
        for (int n = 0; n < 8; n++) {
            const float p0 = __expf(sacc[n*4+0] - SHIFT);
            const float p1 = __expf(sacc[n*4+1] - SHIFT);
            const float p2 = __expf(sacc[n*4+2] - SHIFT);
            const float p3 = __expf(sacc[n*4+3] - SHIFT);
            lsum0 += p0 + p1;
            lsum1 += p2 + p3;
            split2(p0, p1, pah[n*2],   pal[n*2]);
            split2(p2, p3, pah[n*2+1], pal[n*2+1]);
        }

        // ---- O += P V (3-pass bf16 split), this wg's 8 cg groups (128 c) ----
        #pragma unroll
        for (int kk = 0; kk < 4; kk++) {
            const uint32_t* ah = &pah[kk * 4];
            const uint32_t* al = &pal[kk * 4];
            #pragma unroll
            for (int cg = 0; cg < 8; cg++) {
                const uint32_t off = SW(((wg * 8 + cg) * 16 + b_r) * 128 + kk * 32 + b_c2);
                uint32_t vh[4], vl[4];
                ldsm4(vh, kb + OFF_VHI + off);
                ldsm4(vl, kb + OFF_VLO + off);
                float* c0 = &oacc[cg * 8];
                float* c1 = &oacc[cg * 8 + 4];
                mma16816(c0, ah, vh + 0); mma16816(c1, ah, vh + 2);
                mma16816(c0, al, vh + 0); mma16816(c1, al, vh + 2);
                mma16816(c0, ah, vl + 0); mma16816(c1, ah, vl + 2);
            }
        }

        __syncthreads();
        if (t + 2 < NT) {
            load_K(sb + SM_BUF0 + buf * BUF_SZ, b, (t + 2) * TJ, tid);
            load_V(sb + SM_BUF0 + buf * BUF_SZ, b, (t + 2) * TJ, tid);
        }
        CP_COMMIT();
    }

    // ---- reduce l across the quad owning each row ----
    lsum0 += __shfl_xor_sync(0xffffffffu, lsum0, 1);
    lsum0 += __shfl_xor_sync(0xffffffffu, lsum0, 2);
    lsum1 += __shfl_xor_sync(0xffffffffu, lsum1, 1);
    lsum1 += __shfl_xor_sync(0xffffffffu, lsum1, 2);

    const float kv   = kscal[0];
    const float inva = kv / lsum0;
    const float invb = kv / lsum1;

    const int rowa = row0 + mwarp * 16 + (lane >> 2);
    const int rowb = rowa + 8;
    const size_t ga = (size_t)b * HW_ + rowa;
    const size_t gb = (size_t)b * HW_ + rowb;
    const int cbase = wg * 128 + (lane & 3) * 2;

    #pragma unroll
    for (int m = 0; m < 16; m++) {
        const int c = cbase + m * 8;
        const float2 xa = *(const float2*)&x[ga * 256 + c];
        const float2 xb = *(const float2*)&x[gb * 256 + c];
        float2 oa, ob;
        oa.x = fmaf(oacc[m*4+0], inva, xa.x);
        oa.y = fmaf(oacc[m*4+1], inva, xa.y);
        ob.x = fmaf(oacc[m*4+2], invb, xb.x);
        ob.y = fmaf(oacc[m*4+3], invb, xb.y);
        *(float2*)&out[ga * 512 + c] = oa;
        *(float2*)&out[gb * 512 + c] = ob;
    }

    // g passthrough (cols 256..511)
    for (int i = tid; i < 128 * 64; i += THREADS) {
        const int r = i >> 6, v4 = i & 63;
        const float4 gg = ((const float4*)g)[((size_t)b * HW_ + row0 + r) * 64 + v4];
        ((float4*)out)[(((size_t)b * HW_ + row0 + r) * 128) + 64 + v4] = gg;
    }
}

extern "C" void kernel_launch(void* const* d_in, const int* in_sizes, int n_in,
                              void* d_out, int out_size)
{
    const float* g  = (const float*)d_in[0];
    const float* x  = (const float*)d_in[1];
    const float* xq = (const float*)d_in[2];
    const float* pg = (const float*)d_in[3];
    const float* xv = (const float*)d_in[4];
    const float* k  = (const float*)d_in[5];
    float* out = (float*)d_out;

    conv_k_kernel<<<512, 256>>>(xq);
    conv_v_kernel<<<dim3(128, 8, 4), dim3(32, 8)>>>(xv);

    cudaFuncSetAttribute(attn_mma_kernel, cudaFuncAttributeMaxDynamicSharedMemorySize, SM_TOTAL);
    attn_mma_kernel<<<128, THREADS, SM_TOTAL>>>(g, x, pg, k, out);
}

// round 8
// speedup vs baseline: 1.3711x; 1.3711x over previous
#include <cuda_runtime.h>
#include <cuda_bf16.h>
#include <cstdint>

#define B_      4
#define HW_     4096
#define C_      256
#define D_      64
#define TJ      64
#define NT      (HW_/TJ)
#define THREADS 256
#define SHIFT   28.0f

// dynamic smem layout (bytes)
#define SM_QHI  0
#define SM_QLO  16384
#define SM_BUF0 32768
#define OFF_KHI 0
#define OFF_KLO 8192
#define OFF_VHI 16384
#define OFF_VLO 49152
#define BUF_SZ  81920
#define SM_TOTAL (SM_BUF0 + 2*BUF_SZ)   // 196608 B

#define SW(x) ((x) ^ (((x) >> 3) & 0x70))

// pre-converted bf16 splits
__device__ __align__(16) __nv_bfloat16 g_Khi[B_*HW_*D_];
__device__ __align__(16) __nv_bfloat16 g_Klo[B_*HW_*D_];
__device__ __align__(16) __nv_bfloat16 g_Vthi[B_*C_*HW_];   // [b][c][j]
__device__ __align__(16) __nv_bfloat16 g_Vtlo[B_*C_*HW_];

__device__ __forceinline__ uint32_t smem_u32(const void* p) {
    uint32_t a;
    asm("{ .reg .u64 t; cvta.to.shared.u64 t, %1; cvt.u32.u64 %0, t; }" : "=r"(a) : "l"(p));
    return a;
}
__device__ __forceinline__ void cp16(uint32_t dst, const void* src) {
    asm volatile("cp.async.cg.shared.global [%0], [%1], 16;" :: "r"(dst), "l"(src));
}
#define CP_COMMIT() asm volatile("cp.async.commit_group;" ::: "memory")
#define CP_WAIT1()  asm volatile("cp.async.wait_group 1;" ::: "memory")
#define CP_WAIT0()  asm volatile("cp.async.wait_group 0;" ::: "memory")

__device__ __forceinline__ void ldsm4(uint32_t* r, uint32_t addr) {
    asm volatile("ldmatrix.sync.aligned.m8n8.x4.shared.b16 {%0,%1,%2,%3}, [%4];"
                 : "=r"(r[0]), "=r"(r[1]), "=r"(r[2]), "=r"(r[3]) : "r"(addr));
}
__device__ __forceinline__ void mma16816(float* c, const uint32_t* a, const uint32_t* b) {
    asm volatile("mma.sync.aligned.m16n8k16.row.col.f32.bf16.bf16.f32 "
                 "{%0,%1,%2,%3}, {%4,%5,%6,%7}, {%8,%9}, {%0,%1,%2,%3};"
                 : "+f"(c[0]), "+f"(c[1]), "+f"(c[2]), "+f"(c[3])
                 : "r"(a[0]), "r"(a[1]), "r"(a[2]), "r"(a[3]), "r"(b[0]), "r"(b[1]));
}

// pack two floats -> bf16x2 (lo half = a)
__device__ __forceinline__ uint32_t pk2(float a, float b) {
    uint32_t r;
    asm("cvt.rn.bf16x2.f32 %0, %1, %2;" : "=r"(r) : "f"(b), "f"(a));
    return r;
}
__device__ __forceinline__ void split2(float a, float b, uint32_t& hi, uint32_t& lo) {
    hi = pk2(a, b);
    float ra = a - __uint_as_float(hi << 16);
    float rb = b - __uint_as_float(hi & 0xffff0000u);
    lo = pk2(ra, rb);
}

// ---- pre-kernel: split x_query -> Khi/Klo (512*256*8 = exactly 1048576 elems) ----
__global__ void __launch_bounds__(256) conv_k_kernel(const float* __restrict__ xq) {
    size_t id = (size_t)blockIdx.x * 256 + threadIdx.x;
    const float4* src = (const float4*)xq + id * 2;
    float4 a = src[0], b = src[1];
    uint4 hi, lo;
    split2(a.x, a.y, hi.x, lo.x);
    split2(a.z, a.w, hi.y, lo.y);
    split2(b.x, b.y, hi.z, lo.z);
    split2(b.z, b.w, hi.w, lo.w);
    ((uint4*)g_Khi)[id] = hi;
    ((uint4*)g_Klo)[id] = lo;
}

// ---- pre-kernel: transpose+split x_value -> Vthi/Vtlo ----
__global__ void __launch_bounds__(256) conv_v_kernel(const float* __restrict__ xv) {
    __shared__ float tile[32][33];
    const int j0 = blockIdx.x * 32, c0 = blockIdx.y * 32, b = blockIdx.z;
    const int tx = threadIdx.x, ty = threadIdx.y;   // 32 x 8
    #pragma unroll
    for (int r = 0; r < 4; r++) {
        const int j = j0 + ty + r * 8;
        tile[ty + r * 8][tx] = xv[((size_t)(b * HW_ + j)) * C_ + c0 + tx];
    }
    __syncthreads();
    #pragma unroll
    for (int r = 0; r < 4; r++) {
        const int c = c0 + ty + r * 8;
        const float v = tile[tx][ty + r * 8];
        const __nv_bfloat16 h = __float2bfloat16(v);
        const size_t o = ((size_t)(b * C_ + c)) * HW_ + j0 + tx;
        g_Vthi[o] = h;
        g_Vtlo[o] = __float2bfloat16(v - __bfloat162float(h));
    }
}

__device__ __forceinline__ void load_K(uint32_t kbase, int b, int jt, int tid) {
    #pragma unroll
    for (int k = 0; k < 4; k++) {
        const int i = tid + k * 256;               // 1024 x 16B (hi+lo)
        const int half = i >> 9, rem = i & 511, row = rem >> 3, ch = rem & 7;
        const __nv_bfloat16* s = (half ? g_Klo : g_Khi)
                               + (((size_t)(b * HW_ + jt + row)) << 6) + ch * 8;
        cp16(kbase + (half ? OFF_KLO : OFF_KHI) + SW(row * 128 + ch * 16), s);
    }
}
__device__ __forceinline__ void load_V(uint32_t vbase, int b, int jt, int tid) {
    #pragma unroll
    for (int k = 0; k < 16; k++) {
        const int i = tid + k * 256;               // 4096 x 16B (hi+lo)
        const int half = i >> 11, rem = i & 2047, row = rem >> 3, ch = rem & 7;
        const __nv_bfloat16* s = (half ? g_Vtlo : g_Vthi)
                               + ((size_t)(b * C_ + row)) * HW_ + jt + ch * 8;
        cp16(vbase + (half ? OFF_VLO : OFF_VHI) + SW(row * 128 + ch * 16), s);
    }
}

// S = Q K^T over one 64-j tile, 3-pass bf16 split
__device__ __forceinline__ void compute_S(float* sacc, uint32_t kb,
                                          const uint32_t* qoffh, const uint32_t* qoffl,
                                          int b_r, int b_c2) {
    #pragma unroll
    for (int i = 0; i < 32; i++) sacc[i] = 0.0f;
    #pragma unroll
    for (int kk = 0; kk < 4; kk++) {
        uint32_t qh[4], ql[4];
        ldsm4(qh, qoffh[kk]);
        ldsm4(ql, qoffl[kk]);
        #pragma unroll
        for (int ng = 0; ng < 4; ng++) {
            const uint32_t off = SW((ng * 16 + b_r) * 128 + kk * 32 + b_c2);
            uint32_t kh[4], kl[4];
            ldsm4(kh, kb + OFF_KHI + off);
            ldsm4(kl, kb + OFF_KLO + off);
            float* c0 = &sacc[ng * 8];
            float* c1 = &sacc[ng * 8 + 4];
            mma16816(c0, qh, kh + 0); mma16816(c1, qh, kh + 2);
            mma16816(c0, ql, kh + 0); mma16816(c1, ql, kh + 2);
            mma16816(c0, qh, kl + 0); mma16816(c1, qh, kl + 2);
        }
    }
}

// O += P V over one tile, 2-pass (P_hi only; V hi+lo)
__device__ __forceinline__ void compute_PV(float* oacc, const uint32_t* pah, uint32_t kb,
                                           int b_r, int b_c2) {
    #pragma unroll
    for (int kk = 0; kk < 4; kk++) {
        const uint32_t* ah = &pah[kk * 4];
        #pragma unroll
        for (int cg = 0; cg < 16; cg++) {
            const uint32_t off = SW((cg * 16 + b_r) * 128 + kk * 32 + b_c2);
            uint32_t vh[4], vl[4];
            ldsm4(vh, kb + OFF_VHI + off);
            ldsm4(vl, kb + OFF_VLO + off);
            float* c0 = &oacc[cg * 8];
            float* c1 = &oacc[cg * 8 + 4];
            mma16816(c0, ah, vh + 0); mma16816(c1, ah, vh + 2);
            mma16816(c0, ah, vl + 0); mma16816(c1, ah, vl + 2);
        }
    }
}

__global__ void __launch_bounds__(THREADS, 1)
attn_mma_kernel(const float* __restrict__ g, const float* __restrict__ x,
                const float* __restrict__ pg, const float* __restrict__ kscal,
                float* __restrict__ out)
{
    extern __shared__ char smem[];
    const uint32_t sb = smem_u32(smem);
    const int tid  = threadIdx.x;
    const int warp = tid >> 5, lane = tid & 31;
    const int b    = blockIdx.x >> 5;
    const int row0 = (blockIdx.x & 31) * 128;

    const int a_r  = lane & 15;
    const int a_c2 = (lane >> 4) * 16;
    const int b_r  = (lane & 7) + ((lane >> 4) & 1) * 8;
    const int b_c2 = ((lane >> 3) & 1) * 16;

    uint32_t qoffh[4], qoffl[4];
    #pragma unroll
    for (int kk = 0; kk < 4; kk++) {
        const uint32_t o = SW((warp * 16 + a_r) * 128 + kk * 32 + a_c2);
        qoffh[kk] = sb + SM_QHI + o;
        qoffl[kk] = sb + SM_QLO + o;
    }

    // prologue: tile0 -> buf0 (G0), tile1 -> buf1 (G1)
    load_K(sb + SM_BUF0, b, 0, tid);
    load_V(sb + SM_BUF0, b, 0, tid);
    CP_COMMIT();
    load_K(sb + SM_BUF0 + BUF_SZ, b, TJ, tid);
    load_V(sb + SM_BUF0 + BUF_SZ, b, TJ, tid);
    CP_COMMIT();

    // stage Q (load + split) into smem, overlapped with cp.async
    for (int i = tid; i < 4096; i += THREADS) {
        const int r = i >> 5, dp = i & 31;
        const float2 f = *(const float2*)&pg[((size_t)(b * HW_ + row0 + r)) * 64 + dp * 2];
        uint32_t h, l;
        split2(f.x, f.y, h, l);
        const uint32_t o = SW(r * 128 + dp * 4);
        *(uint32_t*)(smem + SM_QHI + o) = h;
        *(uint32_t*)(smem + SM_QLO + o) = l;
    }

    float oacc[128];
    #pragma unroll
    for (int i = 0; i < 128; i++) oacc[i] = 0.0f;
    float lsum0 = 0.0f, lsum1 = 0.0f;
    float sacc[32];

    CP_WAIT0();
    __syncthreads();
    compute_S(sacc, sb + SM_BUF0, qoffh, qoffl, b_r, b_c2);   // S(0)

    for (int t = 0; t < NT - 1; t++) {
        const int buf = t & 1;
        CP_WAIT1();                // ensures V(t) and K(t+1) have arrived
        __syncthreads();           // visibility + all warps done with iter t-1 (K(t) dead)

        // prefetch K(t+2) into this buf's K region (clamped at the tail; harmless reload)
        const int jn = (t + 2 < NT) ? (t + 2) : (NT - 1);
        load_K(sb + SM_BUF0 + buf * BUF_SZ, b, jn * TJ, tid);
        CP_COMMIT();

        // softmax(t): sacc -> P_hi fragments (no P_lo: 2-pass PV)
        uint32_t pah[16];
        #pragma unroll
        for (int n = 0; n < 8; n++) {
            const float p0 = __expf(sacc[n*4+0] - SHIFT);
            const float p1 = __expf(sacc[n*4+1] - SHIFT);
            const float p2 = __expf(sacc[n*4+2] - SHIFT);
            const float p3 = __expf(sacc[n*4+3] - SHIFT);
            lsum0 += p0 + p1;
            lsum1 += p2 + p3;
            pah[n*2]   = pk2(p0, p1);
            pah[n*2+1] = pk2(p2, p3);
        }

        // S(t+1) from the other buffer (overlaps softmax in the scheduler)
        compute_S(sacc, sb + SM_BUF0 + (buf ^ 1) * BUF_SZ, qoffh, qoffl, b_r, b_c2);

        // PV(t)
        compute_PV(oacc, pah, sb + SM_BUF0 + buf * BUF_SZ, b_r, b_c2);

        __syncthreads();           // all warps done reading V(t)
        load_V(sb + SM_BUF0 + buf * BUF_SZ, b, jn * TJ, tid);
        CP_COMMIT();
    }

    // final tile t = NT-1 (buf 1): softmax + PV only
    {
        CP_WAIT0();
        __syncthreads();
        uint32_t pah[16];
        #pragma unroll
        for (int n = 0; n < 8; n++) {
            const float p0 = __expf(sacc[n*4+0] - SHIFT);
            const float p1 = __expf(sacc[n*4+1] - SHIFT);
            const float p2 = __expf(sacc[n*4+2] - SHIFT);
            const float p3 = __expf(sacc[n*4+3] - SHIFT);
            lsum0 += p0 + p1;
            lsum1 += p2 + p3;
            pah[n*2]   = pk2(p0, p1);
            pah[n*2+1] = pk2(p2, p3);
        }
        compute_PV(oacc, pah, sb + SM_BUF0 + BUF_SZ, b_r, b_c2);
    }

    // ---- reduce l across the quad owning each row ----
    lsum0 += __shfl_xor_sync(0xffffffffu, lsum0, 1);
    lsum0 += __shfl_xor_sync(0xffffffffu, lsum0, 2);
    lsum1 += __shfl_xor_sync(0xffffffffu, lsum1, 1);
    lsum1 += __shfl_xor_sync(0xffffffffu, lsum1, 2);

    const float kv   = kscal[0];
    const float inva = kv / lsum0;
    const float invb = kv / lsum1;

    const int rowa = row0 + warp * 16 + (lane >> 2);
    const int rowb = rowa + 8;
    const size_t ga = (size_t)b * HW_ + rowa;
    const size_t gb = (size_t)b * HW_ + rowb;
    const int cbase = (lane & 3) * 2;

    #pragma unroll
    for (int m = 0; m < 32; m++) {
        const int c = m * 8 + cbase;
        const float2 xa = *(const float2*)&x[ga * 256 + c];
        const float2 xb = *(const float2*)&x[gb * 256 + c];
        float2 oa, ob;
        oa.x = fmaf(oacc[m*4+0], inva, xa.x);
        oa.y = fmaf(oacc[m*4+1], inva, xa.y);
        ob.x = fmaf(oacc[m*4+2], invb, xb.x);
        ob.y = fmaf(oacc[m*4+3], invb, xb.y);
        *(float2*)&out[ga * 512 + c] = oa;
        *(float2*)&out[gb * 512 + c] = ob;
    }

    // g passthrough (cols 256..511)
    for (int i = tid; i < 128 * 64; i += THREADS) {
        const int r = i >> 6, v4 = i & 63;
        const float4 gg = ((const float4*)g)[((size_t)b * HW_ + row0 + r) * 64 + v4];
        ((float4*)out)[(((size_t)b * HW_ + row0 + r) * 128) + 64 + v4] = gg;
    }
}

extern "C" void kernel_launch(void* const* d_in, const int* in_sizes, int n_in,
                              void* d_out, int out_size)
{
    const float* g  = (const float*)d_in[0];
    const float* x  = (const float*)d_in[1];
    const float* xq = (const float*)d_in[2];
    const float* pg = (const float*)d_in[3];
    const float* xv = (const float*)d_in[4];
    const float* k  = (const float*)d_in[5];
    float* out = (float*)d_out;

    conv_k_kernel<<<512, 256>>>(xq);
    conv_v_kernel<<<dim3(128, 8, 4), dim3(32, 8)>>>(xv);

    cudaFuncSetAttribute(attn_mma_kernel, cudaFuncAttributeMaxDynamicSharedMemorySize, SM_TOTAL);
    attn_mma_kernel<<<128, THREADS, SM_TOTAL>>>(g, x, pg, k, out);
}

// round 11
// speedup vs baseline: 1.9705x; 1.4372x over previous
#include <cuda_runtime.h>
#include <cuda_bf16.h>
#include <cuda_fp16.h>
#include <cstdint>

#define B_      4
#define HW_     4096
#define C_      256
#define D_      64
#define TJ      64
#define NT      (HW_/TJ)
#define THREADS 256

// dynamic smem layout (bytes)
#define SM_QHI  0
#define SM_QLO  16384
#define SM_BUF0 32768
#define OFF_KHI 0
#define OFF_KLO 8192
#define OFF_V   16384
#define BUF_SZ  49152
#define SM_TOTAL (SM_BUF0 + 2*BUF_SZ)   // 131072 B

#define SW(x) ((x) ^ (((x) >> 3) & 0x70))

// pre-converted operands
__device__ __align__(16) __nv_bfloat16 g_Khi[B_*HW_*D_];
__device__ __align__(16) __nv_bfloat16 g_Klo[B_*HW_*D_];
__device__ __align__(16) __half       g_Vt[B_*C_*HW_];    // [b][c][j] fp16

__device__ __forceinline__ uint32_t smem_u32(const void* p) {
    uint32_t a;
    asm("{ .reg .u64 t; cvta.to.shared.u64 t, %1; cvt.u32.u64 %0, t; }" : "=r"(a) : "l"(p));
    return a;
}
__device__ __forceinline__ void cp16(uint32_t dst, const void* src) {
    asm volatile("cp.async.cg.shared.global [%0], [%1], 16;" :: "r"(dst), "l"(src));
}
#define CP_COMMIT() asm volatile("cp.async.commit_group;" ::: "memory")
#define CP_WAIT1()  asm volatile("cp.async.wait_group 1;" ::: "memory")
#define CP_WAIT0()  asm volatile("cp.async.wait_group 0;" ::: "memory")

__device__ __forceinline__ void ldsm4(uint32_t* r, uint32_t addr) {
    asm volatile("ldmatrix.sync.aligned.m8n8.x4.shared.b16 {%0,%1,%2,%3}, [%4];"
                 : "=r"(r[0]), "=r"(r[1]), "=r"(r[2]), "=r"(r[3]) : "r"(addr));
}
__device__ __forceinline__ void mma_bf16(float* c, const uint32_t* a, const uint32_t* b) {
    asm volatile("mma.sync.aligned.m16n8k16.row.col.f32.bf16.bf16.f32 "
                 "{%0,%1,%2,%3}, {%4,%5,%6,%7}, {%8,%9}, {%0,%1,%2,%3};"
                 : "+f"(c[0]), "+f"(c[1]), "+f"(c[2]), "+f"(c[3])
                 : "r"(a[0]), "r"(a[1]), "r"(a[2]), "r"(a[3]), "r"(b[0]), "r"(b[1]));
}
__device__ __forceinline__ void mma_f16(float* c, const uint32_t* a, const uint32_t* b) {
    asm volatile("mma.sync.aligned.m16n8k16.row.col.f32.f16.f16.f32 "
                 "{%0,%1,%2,%3}, {%4,%5,%6,%7}, {%8,%9}, {%0,%1,%2,%3};"
                 : "+f"(c[0]), "+f"(c[1]), "+f"(c[2]), "+f"(c[3])
                 : "r"(a[0]), "r"(a[1]), "r"(a[2]), "r"(a[3]), "r"(b[0]), "r"(b[1]));
}

// pack two floats -> bf16x2 / f16x2 (lo half = a)
__device__ __forceinline__ uint32_t pk2b(float a, float b) {
    uint32_t r;
    asm("cvt.rn.bf16x2.f32 %0, %1, %2;" : "=r"(r) : "f"(b), "f"(a));
    return r;
}
__device__ __forceinline__ uint32_t pk2h(float a, float b) {
    uint32_t r;
    asm("cvt.rn.f16x2.f32 %0, %1, %2;" : "=r"(r) : "f"(b), "f"(a));
    return r;
}
__device__ __forceinline__ void split2(float a, float b, uint32_t& hi, uint32_t& lo) {
    hi = pk2b(a, b);
    float ra = a - __uint_as_float(hi << 16);
    float rb = b - __uint_as_float(hi & 0xffff0000u);
    lo = pk2b(ra, rb);
}

// ---- pre-kernel: split x_query -> Khi/Klo (512*256*8 = exactly 1048576 elems) ----
__global__ void __launch_bounds__(256) conv_k_kernel(const float* __restrict__ xq) {
    size_t id = (size_t)blockIdx.x * 256 + threadIdx.x;
    const float4* src = (const float4*)xq + id * 2;
    float4 a = src[0], b = src[1];
    uint4 hi, lo;
    split2(a.x, a.y, hi.x, lo.x);
    split2(a.z, a.w, hi.y, lo.y);
    split2(b.x, b.y, hi.z, lo.z);
    split2(b.z, b.w, hi.w, lo.w);
    ((uint4*)g_Khi)[id] = hi;
    ((uint4*)g_Klo)[id] = lo;
}

// ---- pre-kernel: transpose x_value -> fp16 [b][c][j] ----
__global__ void __launch_bounds__(256) conv_v_kernel(const float* __restrict__ xv) {
    __shared__ float tile[32][33];
    const int j0 = blockIdx.x * 32, c0 = blockIdx.y * 32, b = blockIdx.z;
    const int tx = threadIdx.x, ty = threadIdx.y;   // 32 x 8
    #pragma unroll
    for (int r = 0; r < 4; r++) {
        const int j = j0 + ty + r * 8;
        tile[ty + r * 8][tx] = xv[((size_t)(b * HW_ + j)) * C_ + c0 + tx];
    }
    __syncthreads();
    #pragma unroll
    for (int r = 0; r < 4; r++) {
        const int c = c0 + ty + r * 8;
        g_Vt[((size_t)(b * C_ + c)) * HW_ + j0 + tx] = __float2half(tile[tx][ty + r * 8]);
    }
}

__device__ __forceinline__ void load_K(uint32_t kbase, int b, int jt, int tid) {
    #pragma unroll
    for (int k = 0; k < 4; k++) {
        const int i = tid + k * 256;               // 1024 x 16B (hi+lo)
        const int half = i >> 9, rem = i & 511, row = rem >> 3, ch = rem & 7;
        const __nv_bfloat16* s = (half ? g_Klo : g_Khi)
                               + (((size_t)(b * HW_ + jt + row)) << 6) + ch * 8;
        cp16(kbase + (half ? OFF_KLO : OFF_KHI) + SW(row * 128 + ch * 16), s);
    }
}
__device__ __forceinline__ void load_V(uint32_t vbase, int b, int jt, int tid) {
    #pragma unroll
    for (int k = 0; k < 8; k++) {
        const int i = tid + k * 256;               // 2048 x 16B
        const int row = i >> 3, ch = i & 7;
        const __half* s = g_Vt + ((size_t)(b * C_ + row)) * HW_ + jt + ch * 8;
        cp16(vbase + OFF_V + SW(row * 128 + ch * 16), s);
    }
}

// S = Q K^T over one 64-j tile, 3-pass bf16 split
__device__ __forceinline__ void compute_S(float* sacc, uint32_t kb,
                                          const uint32_t* qoffh, const uint32_t* qoffl,
                                          int b_r, int b_c2) {
    #pragma unroll
    for (int i = 0; i < 32; i++) sacc[i] = 0.0f;
    #pragma unroll
    for (int kk = 0; kk < 4; kk++) {
        uint32_t qh[4], ql[4];
        ldsm4(qh, qoffh[kk]);
        ldsm4(ql, qoffl[kk]);
        #pragma unroll
        for (int ng = 0; ng < 4; ng++) {
            const uint32_t off = SW((ng * 16 + b_r) * 128 + kk * 32 + b_c2);
            uint32_t kh[4], kl[4];
            ldsm4(kh, kb + OFF_KHI + off);
            ldsm4(kl, kb + OFF_KLO + off);
            float* c0 = &sacc[ng * 8];
            float* c1 = &sacc[ng * 8 + 4];
            mma_bf16(c0, qh, kh + 0); mma_bf16(c1, qh, kh + 2);
            mma_bf16(c0, ql, kh + 0); mma_bf16(c1, ql, kh + 2);
            mma_bf16(c0, qh, kl + 0); mma_bf16(c1, qh, kl + 2);
        }
    }
}

// O += P V over one tile, single pass fp16
__device__ __forceinline__ void compute_PV(float* oacc, const uint32_t* pah, uint32_t kb,
                                           int b_r, int b_c2) {
    #pragma unroll
    for (int kk = 0; kk < 4; kk++) {
        const uint32_t* ah = &pah[kk * 4];
        #pragma unroll
        for (int cg = 0; cg < 16; cg++) {
            const uint32_t off = SW((cg * 16 + b_r) * 128 + kk * 32 + b_c2);
            uint32_t vh[4];
            ldsm4(vh, kb + OFF_V + off);
            mma_f16(&oacc[cg * 8],     ah, vh + 0);
            mma_f16(&oacc[cg * 8 + 4], ah, vh + 2);
        }
    }
}

// online softmax: update row maxes/sums, rescale oacc, emit fp16 P fragments
__device__ __forceinline__ void softmax_tile(const float* sacc, float* oacc, uint32_t* pah,
                                             float& m0, float& m1, float& lsum0, float& lsum1) {
    float t0 = -1e30f, t1 = -1e30f;
    #pragma unroll
    for (int n = 0; n < 8; n++) {
        t0 = fmaxf(t0, fmaxf(sacc[n*4+0], sacc[n*4+1]));
        t1 = fmaxf(t1, fmaxf(sacc[n*4+2], sacc[n*4+3]));
    }
    t0 = fmaxf(t0, __shfl_xor_sync(0xffffffffu, t0, 1));
    t0 = fmaxf(t0, __shfl_xor_sync(0xffffffffu, t0, 2));
    t1 = fmaxf(t1, __shfl_xor_sync(0xffffffffu, t1, 1));
    t1 = fmaxf(t1, __shfl_xor_sync(0xffffffffu, t1, 2));

    const float nm0 = fmaxf(m0, t0), nm1 = fmaxf(m1, t1);
    const float sc0 = __expf(m0 - nm0), sc1 = __expf(m1 - nm1);
    m0 = nm0; m1 = nm1;

    float ps0 = 0.0f, ps1 = 0.0f;
    #pragma unroll
    for (int n = 0; n < 8; n++) {
        const float p0 = __expf(sacc[n*4+0] - nm0);
        const float p1 = __expf(sacc[n*4+1] - nm0);
        const float p2 = __expf(sacc[n*4+2] - nm1);
        const float p3 = __expf(sacc[n*4+3] - nm1);
        ps0 += p0 + p1;
        ps1 += p2 + p3;
        pah[n*2]   = pk2h(p0, p1);
        pah[n*2+1] = pk2h(p2, p3);
    }
    lsum0 = lsum0 * sc0 + ps0;
    lsum1 = lsum1 * sc1 + ps1;

    #pragma unroll
    for (int m = 0; m < 32; m++) {
        oacc[m*4+0] *= sc0;
        oacc[m*4+1] *= sc0;
        oacc[m*4+2] *= sc1;
        oacc[m*4+3] *= sc1;
    }
}

__global__ void __launch_bounds__(THREADS, 1)
attn_mma_kernel(const float* __restrict__ g, const float* __restrict__ x,
                const float* __restrict__ pg, const float* __restrict__ kscal,
                float* __restrict__ out)
{
    extern __shared__ char smem[];
    const uint32_t sb = smem_u32(smem);
    const int tid  = threadIdx.x;
    const int warp = tid >> 5, lane = tid & 31;
    const int b    = blockIdx.x >> 5;
    const int row0 = (blockIdx.x & 31) * 128;

    const int a_r  = lane & 15;
    const int a_c2 = (lane >> 4) * 16;
    const int b_r  = (lane & 7) + ((lane >> 4) & 1) * 8;
    const int b_c2 = ((lane >> 3) & 1) * 16;

    uint32_t qoffh[4], qoffl[4];
    #pragma unroll
    for (int kk = 0; kk < 4; kk++) {
        const uint32_t o = SW((warp * 16 + a_r) * 128 + kk * 32 + a_c2);
        qoffh[kk] = sb + SM_QHI + o;
        qoffl[kk] = sb + SM_QLO + o;
    }

    // prologue: tile0 -> buf0 (G0), tile1 -> buf1 (G1)
    load_K(sb + SM_BUF0, b, 0, tid);
    load_V(sb + SM_BUF0, b, 0, tid);
    CP_COMMIT();
    load_K(sb + SM_BUF0 + BUF_SZ, b, TJ, tid);
    load_V(sb + SM_BUF0 + BUF_SZ, b, TJ, tid);
    CP_COMMIT();

    // stage Q (load + split) into smem, overlapped with cp.async
    for (int i = tid; i < 4096; i += THREADS) {
        const int r = i >> 5, dp = i & 31;
        const float2 f = *(const float2*)&pg[((size_t)(b * HW_ + row0 + r)) * 64 + dp * 2];
        uint32_t h, l;
        split2(f.x, f.y, h, l);
        const uint32_t o = SW(r * 128 + dp * 4);
        *(uint32_t*)(smem + SM_QHI + o) = h;
        *(uint32_t*)(smem + SM_QLO + o) = l;
    }

    float oacc[128];
    #pragma unroll
    for (int i = 0; i < 128; i++) oacc[i] = 0.0f;
    float lsum0 = 0.0f, lsum1 = 0.0f;
    float m0 = -1e30f, m1 = -1e30f;
    float sacc[32];

    CP_WAIT0();
    __syncthreads();
    compute_S(sacc, sb + SM_BUF0, qoffh, qoffl, b_r, b_c2);   // S(0)

    for (int t = 0; t < NT - 1; t++) {
        const int buf = t & 1;
        CP_WAIT1();                // V(t) and K(t+1) have arrived
        __syncthreads();

        // prefetch K(t+2) into this buf's K region (clamped; harmless reload at tail)
        const int jn = (t + 2 < NT) ? (t + 2) : (NT - 1);
        load_K(sb + SM_BUF0 + buf * BUF_SZ, b, jn * TJ, tid);
        CP_COMMIT();

        uint32_t pah[16];
        softmax_tile(sacc, oacc, pah, m0, m1, lsum0, lsum1);

        // S(t+1) from the other buffer
        compute_S(sacc, sb + SM_BUF0 + (buf ^ 1) * BUF_SZ, qoffh, qoffl, b_r, b_c2);

        // PV(t)
        compute_PV(oacc, pah, sb + SM_BUF0 + buf * BUF_SZ, b_r, b_c2);

        __syncthreads();           // all warps done reading V(t)
        load_V(sb + SM_BUF0 + buf * BUF_SZ, b, jn * TJ, tid);
        CP_COMMIT();
    }

    // final tile (buf 1)
    {
        CP_WAIT0();
        __syncthreads();
        uint32_t pah[16];
        softmax_tile(sacc, oacc, pah, m0, m1, lsum0, lsum1);
        compute_PV(oacc, pah, sb + SM_BUF0 + BUF_SZ, b_r, b_c2);
    }

    // ---- reduce l across the quad owning each row ----
    lsum0 += __shfl_xor_sync(0xffffffffu, lsum0, 1);
    lsum0 += __shfl_xor_sync(0xffffffffu, lsum0, 2);
    lsum1 += __shfl_xor_sync(0xffffffffu, lsum1, 1);
    lsum1 += __shfl_xor_sync(0xffffffffu, lsum1, 2);

    const float kv   = kscal[0];
    const float inva = kv / lsum0;
    const float invb = kv / lsum1;

    const int rowa = row0 + warp * 16 + (lane >> 2);
    const int rowb = rowa + 8;
    const size_t ga = (size_t)b * HW_ + rowa;
    const size_t gb = (size_t)b * HW_ + rowb;
    const int cbase = (lane & 3) * 2;

    #pragma unroll
    for (int m = 0; m < 32; m++) {
        const int c = m * 8 + cbase;
        const float2 xa = *(const float2*)&x[ga * 256 + c];
        const float2 xb = *(const float2*)&x[gb * 256 + c];
        float2 oa, ob;
        oa.x = fmaf(oacc[m*4+0], inva, xa.x);
        oa.y = fmaf(oacc[m*4+1], inva, xa.y);
        ob.x = fmaf(oacc[m*4+2], invb, xb.x);
        ob.y = fmaf(oacc[m*4+3], invb, xb.y);
        *(float2*)&out[ga * 512 + c] = oa;
        *(float2*)&out[gb * 512 + c] = ob;
    }

    // g passthrough (cols 256..511)
    for (int i = tid; i < 128 * 64; i += THREADS) {
        const int r = i >> 6, v4 = i & 63;
        const float4 gg = ((const float4*)g)[((size_t)b * HW_ + row0 + r) * 64 + v4];
        ((float4*)out)[(((size_t)b * HW_ + row0 + r) * 128) + 64 + v4] = gg;
    }
}

extern "C" void kernel_launch(void* const* d_in, const int* in_sizes, int n_in,
                              void* d_out, int out_size)
{
    const float* g  = (const float*)d_in[0];
    const float* x  = (const float*)d_in[1];
    const float* xq = (const float*)d_in[2];
    const float* pg = (const float*)d_in[3];
    const float* xv = (const float*)d_in[4];
    const float* k  = (const float*)d_in[5];
    float* out = (float*)d_out;

    conv_k_kernel<<<512, 256>>>(xq);
    conv_v_kernel<<<dim3(128, 8, 4), dim3(32, 8)>>>(xv);

    cudaFuncSetAttribute(attn_mma_kernel, cudaFuncAttributeMaxDynamicSharedMemorySize, SM_TOTAL);
    attn_mma_kernel<<<128, THREADS, SM_TOTAL>>>(g, x, pg, k, out);
}

// round 12
// speedup vs baseline: 2.1327x; 1.0823x over previous
#include <cuda_runtime.h>
#include <cuda_bf16.h>
#include <cuda_fp16.h>
#include <cstdint>

#define B_      4
#define HW_     4096
#define C_      256
#define D_      64
#define TJ      64
#define NT      (HW_/TJ)
#define THREADS 256

// dynamic smem layout (bytes)
#define SM_QHI  0
#define SM_QLO  16384
#define SM_BUF0 32768
#define OFF_K   0
#define OFF_V   8192
#define BUF_SZ  40960
#define SM_TOTAL (SM_BUF0 + 2*BUF_SZ)   // 114688 B

#define SW(x) ((x) ^ (((x) >> 3) & 0x70))

// pre-converted operands (fp16)
__device__ __align__(16) __half g_Kh[B_*HW_*D_];    // [b][j][d]
__device__ __align__(16) __half g_Vt[B_*C_*HW_];    // [b][c][j]

__device__ __forceinline__ uint32_t smem_u32(const void* p) {
    uint32_t a;
    asm("{ .reg .u64 t; cvta.to.shared.u64 t, %1; cvt.u32.u64 %0, t; }" : "=r"(a) : "l"(p));
    return a;
}
__device__ __forceinline__ void cp16(uint32_t dst, const void* src) {
    asm volatile("cp.async.cg.shared.global [%0], [%1], 16;" :: "r"(dst), "l"(src));
}
#define CP_COMMIT() asm volatile("cp.async.commit_group;" ::: "memory")
#define CP_WAIT1()  asm volatile("cp.async.wait_group 1;" ::: "memory")
#define CP_WAIT0()  asm volatile("cp.async.wait_group 0;" ::: "memory")

__device__ __forceinline__ void ldsm4(uint32_t* r, uint32_t addr) {
    asm volatile("ldmatrix.sync.aligned.m8n8.x4.shared.b16 {%0,%1,%2,%3}, [%4];"
                 : "=r"(r[0]), "=r"(r[1]), "=r"(r[2]), "=r"(r[3]) : "r"(addr));
}
__device__ __forceinline__ void mma_f16(float* c, const uint32_t* a, const uint32_t* b) {
    asm volatile("mma.sync.aligned.m16n8k16.row.col.f32.f16.f16.f32 "
                 "{%0,%1,%2,%3}, {%4,%5,%6,%7}, {%8,%9}, {%0,%1,%2,%3};"
                 : "+f"(c[0]), "+f"(c[1]), "+f"(c[2]), "+f"(c[3])
                 : "r"(a[0]), "r"(a[1]), "r"(a[2]), "r"(a[3]), "r"(b[0]), "r"(b[1]));
}

// pack two floats -> f16x2 (lo half = a)
__device__ __forceinline__ uint32_t pk2h(float a, float b) {
    uint32_t r;
    asm("cvt.rn.f16x2.f32 %0, %1, %2;" : "=r"(r) : "f"(b), "f"(a));
    return r;
}
// fp16 hi/lo split of a float pair
__device__ __forceinline__ void split2h(float a, float b, uint32_t& hi, uint32_t& lo) {
    hi = pk2h(a, b);
    const __half2 h2 = *reinterpret_cast<const __half2*>(&hi);
    lo = pk2h(a - __low2float(h2), b - __high2float(h2));
}

// ---- merged pre-kernel ----
// blocks [0,512):  xq -> g_Kh fp16   (512*256*8 = 1048576 elems)
// blocks [512,4608): xv transpose -> g_Vt fp16 [b][c][j]
__global__ void __launch_bounds__(256) conv_kernel(const float* __restrict__ xq,
                                                   const float* __restrict__ xv) {
    if (blockIdx.x < 512) {
        size_t id = (size_t)blockIdx.x * 256 + threadIdx.x;
        const float4* src = (const float4*)xq + id * 2;
        float4 a = src[0], b = src[1];
        uint4 o;
        o.x = pk2h(a.x, a.y);
        o.y = pk2h(a.z, a.w);
        o.z = pk2h(b.x, b.y);
        o.w = pk2h(b.z, b.w);
        ((uint4*)g_Kh)[id] = o;
        return;
    }
    __shared__ float tile[32][33];
    const int idx = blockIdx.x - 512;
    const int j0 = (idx & 127) * 32, c0 = ((idx >> 7) & 7) * 32, b = idx >> 10;
    const int tx = threadIdx.x & 31, ty = threadIdx.x >> 5;   // 32 x 8
    #pragma unroll
    for (int r = 0; r < 4; r++) {
        const int j = j0 + ty + r * 8;
        tile[ty + r * 8][tx] = xv[((size_t)(b * HW_ + j)) * C_ + c0 + tx];
    }
    __syncthreads();
    #pragma unroll
    for (int r = 0; r < 4; r++) {
        const int c = c0 + ty + r * 8;
        g_Vt[((size_t)(b * C_ + c)) * HW_ + j0 + tx] = __float2half(tile[tx][ty + r * 8]);
    }
}

__device__ __forceinline__ void load_K(uint32_t kbase, int b, int jt, int tid) {
    #pragma unroll
    for (int k = 0; k < 2; k++) {
        const int i = tid + k * 256;               // 512 x 16B
        const int row = i >> 3, ch = i & 7;
        const __half* s = g_Kh + (((size_t)(b * HW_ + jt + row)) << 6) + ch * 8;
        cp16(kbase + OFF_K + SW(row * 128 + ch * 16), s);
    }
}
__device__ __forceinline__ void load_V(uint32_t vbase, int b, int jt, int tid) {
    #pragma unroll
    for (int k = 0; k < 8; k++) {
        const int i = tid + k * 256;               // 2048 x 16B
        const int row = i >> 3, ch = i & 7;
        const __half* s = g_Vt + ((size_t)(b * C_ + row)) * HW_ + jt + ch * 8;
        cp16(vbase + OFF_V + SW(row * 128 + ch * 16), s);
    }
}

// S = Q K^T over one 64-j tile: 2-pass fp16 (q_hi*k + q_lo*k)
__device__ __forceinline__ void compute_S(float* sacc, uint32_t kb,
                                          const uint32_t* qoffh, const uint32_t* qoffl,
                                          int b_r, int b_c2) {
    #pragma unroll
    for (int i = 0; i < 32; i++) sacc[i] = 0.0f;
    #pragma unroll
    for (int kk = 0; kk < 4; kk++) {
        uint32_t qh[4], ql[4];
        ldsm4(qh, qoffh[kk]);
        ldsm4(ql, qoffl[kk]);
        #pragma unroll
        for (int ng = 0; ng < 4; ng++) {
            const uint32_t off = SW((ng * 16 + b_r) * 128 + kk * 32 + b_c2);
            uint32_t kh[4];
            ldsm4(kh, kb + OFF_K + off);
            float* c0 = &sacc[ng * 8];
            float* c1 = &sacc[ng * 8 + 4];
            mma_f16(c0, qh, kh + 0); mma_f16(c1, qh, kh + 2);
            mma_f16(c0, ql, kh + 0); mma_f16(c1, ql, kh + 2);
        }
    }
}

// O += P V over one tile, single pass fp16
__device__ __forceinline__ void compute_PV(float* oacc, const uint32_t* pah, uint32_t kb,
                                           int b_r, int b_c2) {
    #pragma unroll
    for (int kk = 0; kk < 4; kk++) {
        const uint32_t* ah = &pah[kk * 4];
        #pragma unroll
        for (int cg = 0; cg < 16; cg++) {
            const uint32_t off = SW((cg * 16 + b_r) * 128 + kk * 32 + b_c2);
            uint32_t vh[4];
            ldsm4(vh, kb + OFF_V + off);
            mma_f16(&oacc[cg * 8],     ah, vh + 0);
            mma_f16(&oacc[cg * 8 + 4], ah, vh + 2);
        }
    }
}

// online softmax with skip-rescale fast path
__device__ __forceinline__ void softmax_tile(const float* sacc, float* oacc, uint32_t* pah,
                                             float& m0, float& m1, float& lsum0, float& lsum1) {
    float t0 = -1e30f, t1 = -1e30f;
    #pragma unroll
    for (int n = 0; n < 8; n++) {
        t0 = fmaxf(t0, fmaxf(sacc[n*4+0], sacc[n*4+1]));
        t1 = fmaxf(t1, fmaxf(sacc[n*4+2], sacc[n*4+3]));
    }
    t0 = fmaxf(t0, __shfl_xor_sync(0xffffffffu, t0, 1));
    t0 = fmaxf(t0, __shfl_xor_sync(0xffffffffu, t0, 2));
    t1 = fmaxf(t1, __shfl_xor_sync(0xffffffffu, t1, 1));
    t1 = fmaxf(t1, __shfl_xor_sync(0xffffffffu, t1, 2));

    const float nm0 = fmaxf(m0, t0), nm1 = fmaxf(m1, t1);
    if (nm0 > m0 || nm1 > m1) {
        const float sc0 = __expf(m0 - nm0), sc1 = __expf(m1 - nm1);
        lsum0 *= sc0; lsum1 *= sc1;
        #pragma unroll
        for (int m = 0; m < 32; m++) {
            oacc[m*4+0] *= sc0;
            oacc[m*4+1] *= sc0;
            oacc[m*4+2] *= sc1;
            oacc[m*4+3] *= sc1;
        }
        m0 = nm0; m1 = nm1;
    }

    float ps0 = 0.0f, ps1 = 0.0f;
    #pragma unroll
    for (int n = 0; n < 8; n++) {
        const float p0 = __expf(sacc[n*4+0] - m0);
        const float p1 = __expf(sacc[n*4+1] - m0);
        const float p2 = __expf(sacc[n*4+2] - m1);
        const float p3 = __expf(sacc[n*4+3] - m1);
        ps0 += p0 + p1;
        ps1 += p2 + p3;
        pah[n*2]   = pk2h(p0, p1);
        pah[n*2+1] = pk2h(p2, p3);
    }
    lsum0 += ps0;
    lsum1 += ps1;
}

__global__ void __launch_bounds__(THREADS, 1)
attn_mma_kernel(const float* __restrict__ g, const float* __restrict__ x,
                const float* __restrict__ pg, const float* __restrict__ kscal,
                float* __restrict__ out)
{
    extern __shared__ char smem[];
    const uint32_t sb = smem_u32(smem);
    const int tid  = threadIdx.x;
    const int warp = tid >> 5, lane = tid & 31;
    const int b    = blockIdx.x >> 5;
    const int row0 = (blockIdx.x & 31) * 128;

    const int a_r  = lane & 15;
    const int a_c2 = (lane >> 4) * 16;
    const int b_r  = (lane & 7) + ((lane >> 4) & 1) * 8;
    const int b_c2 = ((lane >> 3) & 1) * 16;

    uint32_t qoffh[4], qoffl[4];
    #pragma unroll
    for (int kk = 0; kk < 4; kk++) {
        const uint32_t o = SW((warp * 16 + a_r) * 128 + kk * 32 + a_c2);
        qoffh[kk] = sb + SM_QHI + o;
        qoffl[kk] = sb + SM_QLO + o;
    }

    // prologue: tile0 -> buf0 (G0), tile1 -> buf1 (G1)
    load_K(sb + SM_BUF0, b, 0, tid);
    load_V(sb + SM_BUF0, b, 0, tid);
    CP_COMMIT();
    load_K(sb + SM_BUF0 + BUF_SZ, b, TJ, tid);
    load_V(sb + SM_BUF0 + BUF_SZ, b, TJ, tid);
    CP_COMMIT();

    // stage Q (load + fp16 hi/lo split) into smem, overlapped with cp.async
    for (int i = tid; i < 4096; i += THREADS) {
        const int r = i >> 5, dp = i & 31;
        const float2 f = *(const float2*)&pg[((size_t)(b * HW_ + row0 + r)) * 64 + dp * 2];
        uint32_t h, l;
        split2h(f.x, f.y, h, l);
        const uint32_t o = SW(r * 128 + dp * 4);
        *(uint32_t*)(smem + SM_QHI + o) = h;
        *(uint32_t*)(smem + SM_QLO + o) = l;
    }

    float oacc[128];
    #pragma unroll
    for (int i = 0; i < 128; i++) oacc[i] = 0.0f;
    float lsum0 = 0.0f, lsum1 = 0.0f;
    float m0 = -1e30f, m1 = -1e30f;
    float sacc[32];

    CP_WAIT0();
    __syncthreads();
    compute_S(sacc, sb + SM_BUF0, qoffh, qoffl, b_r, b_c2);   // S(0)

    for (int t = 0; t < NT - 1; t++) {
        const int buf = t & 1;
        CP_WAIT1();                // V(t) and K(t+1) have arrived
        __syncthreads();

        // prefetch K(t+2) into this buf's K region (clamped; harmless reload at tail)
        const int jn = (t + 2 < NT) ? (t + 2) : (NT - 1);
        load_K(sb + SM_BUF0 + buf * BUF_SZ, b, jn * TJ, tid);
        CP_COMMIT();

        uint32_t pah[16];
        softmax_tile(sacc, oacc, pah, m0, m1, lsum0, lsum1);

        // S(t+1) from the other buffer
        compute_S(sacc, sb + SM_BUF0 + (buf ^ 1) * BUF_SZ, qoffh, qoffl, b_r, b_c2);

        // PV(t)
        compute_PV(oacc, pah, sb + SM_BUF0 + buf * BUF_SZ, b_r, b_c2);

        __syncthreads();           // all warps done reading V(t)
        load_V(sb + SM_BUF0 + buf * BUF_SZ, b, jn * TJ, tid);
        CP_COMMIT();
    }

    // final tile (buf 1)
    {
        CP_WAIT0();
        __syncthreads();
        uint32_t pah[16];
        softmax_tile(sacc, oacc, pah, m0, m1, lsum0, lsum1);
        compute_PV(oacc, pah, sb + SM_BUF0 + BUF_SZ, b_r, b_c2);
    }

    // ---- reduce l across the quad owning each row ----
    lsum0 += __shfl_xor_sync(0xffffffffu, lsum0, 1);
    lsum0 += __shfl_xor_sync(0xffffffffu, lsum0, 2);
    lsum1 += __shfl_xor_sync(0xffffffffu, lsum1, 1);
    lsum1 += __shfl_xor_sync(0xffffffffu, lsum1, 2);

    const float kv   = kscal[0];
    const float inva = kv / lsum0;
    const float invb = kv / lsum1;

    const int rowa = row0 + warp * 16 + (lane >> 2);
    const int rowb = rowa + 8;
    const size_t ga = (size_t)b * HW_ + rowa;
    const size_t gb = (size_t)b * HW_ + rowb;
    const int cbase = (lane & 3) * 2;

    #pragma unroll
    for (int m = 0; m < 32; m++) {
        const int c = m * 8 + cbase;
        const float2 xa = *(const float2*)&x[ga * 256 + c];
        const float2 xb = *(const float2*)&x[gb * 256 + c];
        float2 oa, ob;
        oa.x = fmaf(oacc[m*4+0], inva, xa.x);
        oa.y = fmaf(oacc[m*4+1], inva, xa.y);
        ob.x = fmaf(oacc[m*4+2], invb, xb.x);
        ob.y = fmaf(oacc[m*4+3], invb, xb.y);
        *(float2*)&out[ga * 512 + c] = oa;
        *(float2*)&out[gb * 512 + c] = ob;
    }

    // g passthrough (cols 256..511)
    for (int i = tid; i < 128 * 64; i += THREADS) {
        const int r = i >> 6, v4 = i & 63;
        const float4 gg = ((const float4*)g)[((size_t)b * HW_ + row0 + r) * 64 + v4];
        ((float4*)out)[(((size_t)b * HW_ + row0 + r) * 128) + 64 + v4] = gg;
    }
}

extern "C" void kernel_launch(void* const* d_in, const int* in_sizes, int n_in,
                              void* d_out, int out_size)
{
    const float* g  = (const float*)d_in[0];
    const float* x  = (const float*)d_in[1];
    const float* xq = (const float*)d_in[2];
    const float* pg = (const float*)d_in[3];
    const float* xv = (const float*)d_in[4];
    const float* k  = (const float*)d_in[5];
    float* out = (float*)d_out;

    conv_kernel<<<4608, 256>>>(xq, xv);

    cudaFuncSetAttribute(attn_mma_kernel, cudaFuncAttributeMaxDynamicSharedMemorySize, SM_TOTAL);
    attn_mma_kernel<<<128, THREADS, SM_TOTAL>>>(g, x, pg, k, out);
}

// round 15
// speedup vs baseline: 2.2440x; 1.0522x over previous
#include <cuda_runtime.h>
#include <cuda_bf16.h>
#include <cuda_fp16.h>
#include <cstdint>

#define B_      4
#define HW_     4096
#define C_      256
#define D_      64
#define TJ      64
#define NT      (HW_/TJ)
#define THREADS 256

// dynamic smem layout (bytes)
#define SM_QHI  0
#define SM_QLO  16384
#define SM_BUF0 32768
#define OFF_K   0
#define OFF_V   8192
#define BUF_SZ  40960
#define SM_TOTAL (SM_BUF0 + 2*BUF_SZ)   // 114688 B

#define SW(x) ((x) ^ (((x) >> 3) & 0x70))

// pre-converted operands (fp16)
__device__ __align__(16) __half g_Kh[B_*HW_*D_];    // [b][j][d]
__device__ __align__(16) __half g_Vt[B_*C_*HW_];    // [b][c][j]

__device__ __forceinline__ uint32_t smem_u32(const void* p) {
    uint32_t a;
    asm("{ .reg .u64 t; cvta.to.shared.u64 t, %1; cvt.u32.u64 %0, t; }" : "=r"(a) : "l"(p));
    return a;
}
__device__ __forceinline__ void cp16(uint32_t dst, const void* src) {
    asm volatile("cp.async.cg.shared.global [%0], [%1], 16;" :: "r"(dst), "l"(src));
}
#define CP_COMMIT() asm volatile("cp.async.commit_group;" ::: "memory")
#define CP_WAIT1()  asm volatile("cp.async.wait_group 1;" ::: "memory")
#define CP_WAIT0()  asm volatile("cp.async.wait_group 0;" ::: "memory")

__device__ __forceinline__ void ldsm4(uint32_t* r, uint32_t addr) {
    asm volatile("ldmatrix.sync.aligned.m8n8.x4.shared.b16 {%0,%1,%2,%3}, [%4];"
                 : "=r"(r[0]), "=r"(r[1]), "=r"(r[2]), "=r"(r[3]) : "r"(addr));
}
__device__ __forceinline__ void mma_f16(float* c, const uint32_t* a, const uint32_t* b) {
    asm volatile("mma.sync.aligned.m16n8k16.row.col.f32.f16.f16.f32 "
                 "{%0,%1,%2,%3}, {%4,%5,%6,%7}, {%8,%9}, {%0,%1,%2,%3};"
                 : "+f"(c[0]), "+f"(c[1]), "+f"(c[2]), "+f"(c[3])
                 : "r"(a[0]), "r"(a[1]), "r"(a[2]), "r"(a[3]), "r"(b[0]), "r"(b[1]));
}

// pack two floats -> f16x2 (lo half = a)
__device__ __forceinline__ uint32_t pk2h(float a, float b) {
    uint32_t r;
    asm("cvt.rn.f16x2.f32 %0, %1, %2;" : "=r"(r) : "f"(b), "f"(a));
    return r;
}
// fp16 hi/lo split of a float pair
__device__ __forceinline__ void split2h(float a, float b, uint32_t& hi, uint32_t& lo) {
    hi = pk2h(a, b);
    const __half2 h2 = *reinterpret_cast<const __half2*>(&hi);
    lo = pk2h(a - __low2float(h2), b - __high2float(h2));
}

// ---- merged pre-kernel ----
__global__ void __launch_bounds__(256) conv_kernel(const float* __restrict__ xq,
                                                   const float* __restrict__ xv) {
    if (blockIdx.x < 512) {
        size_t id = (size_t)blockIdx.x * 256 + threadIdx.x;
        const float4* src = (const float4*)xq + id * 2;
        float4 a = src[0], b = src[1];
        uint4 o;
        o.x = pk2h(a.x, a.y);
        o.y = pk2h(a.z, a.w);
        o.z = pk2h(b.x, b.y);
        o.w = pk2h(b.z, b.w);
        ((uint4*)g_Kh)[id] = o;
        return;
    }
    __shared__ float tile[32][33];
    const int idx = blockIdx.x - 512;
    const int j0 = (idx & 127) * 32, c0 = ((idx >> 7) & 7) * 32, b = idx >> 10;
    const int tx = threadIdx.x & 31, ty = threadIdx.x >> 5;   // 32 x 8
    #pragma unroll
    for (int r = 0; r < 4; r++) {
        const int j = j0 + ty + r * 8;
        tile[ty + r * 8][tx] = xv[((size_t)(b * HW_ + j)) * C_ + c0 + tx];
    }
    __syncthreads();
    #pragma unroll
    for (int r = 0; r < 4; r++) {
        const int c = c0 + ty + r * 8;
        g_Vt[((size_t)(b * C_ + c)) * HW_ + j0 + tx] = __float2half(tile[tx][ty + r * 8]);
    }
}

__device__ __forceinline__ void load_K(uint32_t kbase, int b, int jt, int tid) {
    #pragma unroll
    for (int k = 0; k < 2; k++) {
        const int i = tid + k * 256;               // 512 x 16B
        const int row = i >> 3, ch = i & 7;
        const __half* s = g_Kh + (((size_t)(b * HW_ + jt + row)) << 6) + ch * 8;
        cp16(kbase + OFF_K + SW(row * 128 + ch * 16), s);
    }
}
__device__ __forceinline__ void load_V(uint32_t vbase, int b, int jt, int tid) {
    #pragma unroll
    for (int k = 0; k < 8; k++) {
        const int i = tid + k * 256;               // 2048 x 16B
        const int row = i >> 3, ch = i & 7;
        const __half* s = g_Vt + ((size_t)(b * C_ + row)) * HW_ + jt + ch * 8;
        cp16(vbase + OFF_V + SW(row * 128 + ch * 16), s);
    }
}

// S(prologue) = Q K^T, 2-pass fp16, Q from registers
__device__ __forceinline__ void compute_S(float* sacc, uint32_t kb,
                                          const uint32_t* Qh, const uint32_t* Ql,
                                          int b_r, int b_c2) {
    #pragma unroll
    for (int i = 0; i < 32; i++) sacc[i] = 0.0f;
    #pragma unroll
    for (int kk = 0; kk < 4; kk++) {
        #pragma unroll
        for (int ng = 0; ng < 4; ng++) {
            const uint32_t off = SW((ng * 16 + b_r) * 128 + kk * 32 + b_c2);
            uint32_t kh[4];
            ldsm4(kh, kb + OFF_K + off);
            float* c0 = &sacc[ng * 8];
            float* c1 = &sacc[ng * 8 + 4];
            mma_f16(c0, &Qh[kk*4], kh + 0); mma_f16(c1, &Qh[kk*4], kh + 2);
            mma_f16(c0, &Ql[kk*4], kh + 0); mma_f16(c1, &Ql[kk*4], kh + 2);
        }
    }
}

// merged: S(t+1) into sacc (from kbS) interleaved with PV(t) into oacc (from kbPV)
__device__ __forceinline__ void compute_S_PV(float* sacc, float* oacc,
                                             uint32_t kbS, uint32_t kbPV,
                                             const uint32_t* Qh, const uint32_t* Ql,
                                             const uint32_t* pah,
                                             int b_r, int b_c2) {
    #pragma unroll
    for (int i = 0; i < 32; i++) sacc[i] = 0.0f;
    #pragma unroll
    for (int kk = 0; kk < 4; kk++) {
        const uint32_t* ah = &pah[kk * 4];
        // S chunk: 4 ldsm + 16 mma into sacc
        #pragma unroll
        for (int ng = 0; ng < 4; ng++) {
            const uint32_t off = SW((ng * 16 + b_r) * 128 + kk * 32 + b_c2);
            uint32_t kh[4];
            ldsm4(kh, kbS + OFF_K + off);
            float* c0 = &sacc[ng * 8];
            float* c1 = &sacc[ng * 8 + 4];
            mma_f16(c0, &Qh[kk*4], kh + 0); mma_f16(c1, &Qh[kk*4], kh + 2);
            mma_f16(c0, &Ql[kk*4], kh + 0); mma_f16(c1, &Ql[kk*4], kh + 2);
        }
        // PV chunk: 16 ldsm + 32 mma into oacc (independent of S chunk)
        #pragma unroll
        for (int cg = 0; cg < 16; cg++) {
            const uint32_t off = SW((cg * 16 + b_r) * 128 + kk * 32 + b_c2);
            uint32_t vh[4];
            ldsm4(vh, kbPV + OFF_V + off);
            mma_f16(&oacc[cg * 8],     ah, vh + 0);
            mma_f16(&oacc[cg * 8 + 4], ah, vh + 2);
        }
    }
}

// PV only (tail tile)
__device__ __forceinline__ void compute_PV(float* oacc, const uint32_t* pah, uint32_t kb,
                                           int b_r, int b_c2) {
    #pragma unroll
    for (int kk = 0; kk < 4; kk++) {
        const uint32_t* ah = &pah[kk * 4];
        #pragma unroll
        for (int cg = 0; cg < 16; cg++) {
            const uint32_t off = SW((cg * 16 + b_r) * 128 + kk * 32 + b_c2);
            uint32_t vh[4];
            ldsm4(vh, kb + OFF_V + off);
            mma_f16(&oacc[cg * 8],     ah, vh + 0);
            mma_f16(&oacc[cg * 8 + 4], ah, vh + 2);
        }
    }
}

// online softmax with skip-rescale fast path
__device__ __forceinline__ void softmax_tile(const float* sacc, float* oacc, uint32_t* pah,
                                             float& m0, float& m1, float& lsum0, float& lsum1) {
    float t0 = -1e30f, t1 = -1e30f;
    #pragma unroll
    for (int n = 0; n < 8; n++) {
        t0 = fmaxf(t0, fmaxf(sacc[n*4+0], sacc[n*4+1]));
        t1 = fmaxf(t1, fmaxf(sacc[n*4+2], sacc[n*4+3]));
    }
    t0 = fmaxf(t0, __shfl_xor_sync(0xffffffffu, t0, 1));
    t0 = fmaxf(t0, __shfl_xor_sync(0xffffffffu, t0, 2));
    t1 = fmaxf(t1, __shfl_xor_sync(0xffffffffu, t1, 1));
    t1 = fmaxf(t1, __shfl_xor_sync(0xffffffffu, t1, 2));

    const float nm0 = fmaxf(m0, t0), nm1 = fmaxf(m1, t1);
    if (nm0 > m0 || nm1 > m1) {
        const float sc0 = __expf(m0 - nm0), sc1 = __expf(m1 - nm1);
        lsum0 *= sc0; lsum1 *= sc1;
        #pragma unroll
        for (int m = 0; m < 32; m++) {
            oacc[m*4+0] *= sc0;
            oacc[m*4+1] *= sc0;
            oacc[m*4+2] *= sc1;
            oacc[m*4+3] *= sc1;
        }
        m0 = nm0; m1 = nm1;
    }

    float ps0 = 0.0f, ps1 = 0.0f;
    #pragma unroll
    for (int n = 0; n < 8; n++) {
        const float p0 = __expf(sacc[n*4+0] - m0);
        const float p1 = __expf(sacc[n*4+1] - m0);
        const float p2 = __expf(sacc[n*4+2] - m1);
        const float p3 = __expf(sacc[n*4+3] - m1);
        ps0 += p0 + p1;
        ps1 += p2 + p3;
        pah[n*2]   = pk2h(p0, p1);
        pah[n*2+1] = pk2h(p2, p3);
    }
    lsum0 += ps0;
    lsum1 += ps1;
}

__global__ void __launch_bounds__(THREADS, 1)
attn_mma_kernel(const float* __restrict__ g, const float* __restrict__ x,
                const float* __restrict__ pg, const float* __restrict__ kscal,
                float* __restrict__ out)
{
    extern __shared__ char smem[];
    const uint32_t sb = smem_u32(smem);
    const int tid  = threadIdx.x;
    const int warp = tid >> 5, lane = tid & 31;
    const int b    = blockIdx.x >> 5;
    const int row0 = (blockIdx.x & 31) * 128;

    const int a_r  = lane & 15;
    const int a_c2 = (lane >> 4) * 16;
    const int b_r  = (lane & 7) + ((lane >> 4) & 1) * 8;
    const int b_c2 = ((lane >> 3) & 1) * 16;

    // prologue: tile0 -> buf0 (G0), tile1 -> buf1 (G1)
    load_K(sb + SM_BUF0, b, 0, tid);
    load_V(sb + SM_BUF0, b, 0, tid);
    CP_COMMIT();
    load_K(sb + SM_BUF0 + BUF_SZ, b, TJ, tid);
    load_V(sb + SM_BUF0 + BUF_SZ, b, TJ, tid);
    CP_COMMIT();

    // stage Q (load + fp16 hi/lo split) into smem, overlapped with cp.async
    for (int i = tid; i < 4096; i += THREADS) {
        const int r = i >> 5, dp = i & 31;
        const float2 f = *(const float2*)&pg[((size_t)(b * HW_ + row0 + r)) * 64 + dp * 2];
        uint32_t h, l;
        split2h(f.x, f.y, h, l);
        const uint32_t o = SW(r * 128 + dp * 4);
        *(uint32_t*)(smem + SM_QHI + o) = h;
        *(uint32_t*)(smem + SM_QLO + o) = l;
    }
    __syncthreads();   // Q smem visible to all warps

    // hoist Q fragments into registers (tile-invariant)
    uint32_t Qh[16], Ql[16];
    #pragma unroll
    for (int kk = 0; kk < 4; kk++) {
        const uint32_t o = SW((warp * 16 + a_r) * 128 + kk * 32 + a_c2);
        ldsm4(&Qh[kk*4], sb + SM_QHI + o);
        ldsm4(&Ql[kk*4], sb + SM_QLO + o);
    }

    float oacc[128];
    #pragma unroll
    for (int i = 0; i < 128; i++) oacc[i] = 0.0f;
    float lsum0 = 0.0f, lsum1 = 0.0f;
    float m0 = -1e30f, m1 = -1e30f;
    float sacc[32];

    CP_WAIT0();
    __syncthreads();
    compute_S(sacc, sb + SM_BUF0, Qh, Ql, b_r, b_c2);   // S(0)

    for (int t = 0; t < NT - 1; t++) {
        const int buf = t & 1;
        CP_WAIT1();                // V(t) and K(t+1) have arrived
        __syncthreads();

        // prefetch K(t+2) into this buf's K region (clamped; harmless reload at tail)
        const int jn = (t + 2 < NT) ? (t + 2) : (NT - 1);
        load_K(sb + SM_BUF0 + buf * BUF_SZ, b, jn * TJ, tid);
        CP_COMMIT();

        uint32_t pah[16];
        softmax_tile(sacc, oacc, pah, m0, m1, lsum0, lsum1);

        // interleaved S(t+1) [buf^1] + PV(t) [buf]
        compute_S_PV(sacc, oacc,
                     sb + SM_BUF0 + (buf ^ 1) * BUF_SZ,
                     sb + SM_BUF0 + buf * BUF_SZ,
                     Qh, Ql, pah, b_r, b_c2);

        __syncthreads();           // all warps done reading V(t)
        load_V(sb + SM_BUF0 + buf * BUF_SZ, b, jn * TJ, tid);
        CP_COMMIT();
    }

    // final tile (buf 1)
    {
        CP_WAIT0();
        __syncthreads();
        uint32_t pah[16];
        softmax_tile(sacc, oacc, pah, m0, m1, lsum0, lsum1);
        compute_PV(oacc, pah, sb + SM_BUF0 + BUF_SZ, b_r, b_c2);
    }

    // ---- reduce l across the quad owning each row ----
    lsum0 += __shfl_xor_sync(0xffffffffu, lsum0, 1);
    lsum0 += __shfl_xor_sync(0xffffffffu, lsum0, 2);
    lsum1 += __shfl_xor_sync(0xffffffffu, lsum1, 1);
    lsum1 += __shfl_xor_sync(0xffffffffu, lsum1, 2);

    const float kv   = kscal[0];
    const float inva = kv / lsum0;
    const float invb = kv / lsum1;

    const int rowa = row0 + warp * 16 + (lane >> 2);
    const int rowb = rowa + 8;
    const size_t ga = (size_t)b * HW_ + rowa;
    const size_t gb = (size_t)b * HW_ + rowb;
    const int cbase = (lane & 3) * 2;

    #pragma unroll
    for (int m = 0; m < 32; m++) {
        const int c = m * 8 + cbase;
        const float2 xa = *(const float2*)&x[ga * 256 + c];
        const float2 xb = *(const float2*)&x[gb * 256 + c];
        float2 oa, ob;
        oa.x = fmaf(oacc[m*4+0], inva, xa.x);
        oa.y = fmaf(oacc[m*4+1], inva, xa.y);
        ob.x = fmaf(oacc[m*4+2], invb, xb.x);
        ob.y = fmaf(oacc[m*4+3], invb, xb.y);
        *(float2*)&out[ga * 512 + c] = oa;
        *(float2*)&out[gb * 512 + c] = ob;
    }

    // g passthrough (cols 256..511)
    for (int i = tid; i < 128 * 64; i += THREADS) {
        const int r = i >> 6, v4 = i & 63;
        const float4 gg = ((const float4*)g)[((size_t)b * HW_ + row0 + r) * 64 + v4];
        ((float4*)out)[(((size_t)b * HW_ + row0 + r) * 128) + 64 + v4] = gg;
    }
}

extern "C" void kernel_launch(void* const* d_in, const int* in_sizes, int n_in,
                              void* d_out, int out_size)
{
    const float* g  = (const float*)d_in[0];
    const float* x  = (const float*)d_in[1];
    const float* xq = (const float*)d_in[2];
    const float* pg = (const float*)d_in[3];
    const float* xv = (const float*)d_in[4];
    const float* k  = (const float*)d_in[5];
    float* out = (float*)d_out;

    conv_kernel<<<4608, 256>>>(xq, xv);

    cudaFuncSetAttribute(attn_mma_kernel, cudaFuncAttributeMaxDynamicSharedMemorySize, SM_TOTAL);
    attn_mma_kernel<<<128, THREADS, SM_TOTAL>>>(g, x, pg, k, out);
}